// round 5
// baseline (speedup 1.0000x reference)
#include <cuda_runtime.h>
#include <cuda_bf16.h>
#include <cstdint>

// Problem constants (from reference setup_inputs)
#define BATCH  4096
#define CWDIM  1024
#define CODES  128     // C
#define BOOK   256     // K
#define DEMB   8       // D

// ---------------------------------------------------------------------------
// Fused kernel (R2 structure + evict-first streaming stores).
// grid = (BATCH/256, CODES), block = 256 threads, one c per block.
// score(k) = 0.5*||c_k||^2 - x . c_k   (same argmin as full distance)
// ---------------------------------------------------------------------------
__global__ void __launch_bounds__(256)
vq_fused_kernel(const float* __restrict__ x,
                const float* __restrict__ cb,
                float* __restrict__ cw_embed,
                float* __restrict__ one_hot)
{
    __shared__ float4        s_cb[BOOK * 2];   // codebook[c]: 256 rows x 8 floats
    __shared__ float         s_c2h[BOOK];      // 0.5 * ||c_k||^2
    __shared__ unsigned char s_idx[256];       // argmin index per b-row

    const int c = blockIdx.y;
    const int t = threadIdx.x;

    // ---- Stage codebook[c] into smem ----
    const float4* cb4 = reinterpret_cast<const float4*>(cb + (size_t)c * BOOK * DEMB);
    float4 r0 = cb4[t * 2 + 0];
    float4 r1 = cb4[t * 2 + 1];
    s_cb[t * 2 + 0] = r0;
    s_cb[t * 2 + 1] = r1;
    s_c2h[t] = 0.5f * (r0.x * r0.x + r0.y * r0.y + r0.z * r0.z + r0.w * r0.w +
                       r1.x * r1.x + r1.y * r1.y + r1.z * r1.z + r1.w * r1.w);
    __syncthreads();

    const int b = blockIdx.x * 256 + t;

    // ---- Argmin over K=256 (x loaded evict-first; read exactly once) ----
    const float4* xp = reinterpret_cast<const float4*>(x + (size_t)b * CWDIM + c * DEMB);
    float4 x0 = __ldcs(xp + 0);
    float4 x1 = __ldcs(xp + 1);
    const float xn0 = -x0.x, xn1 = -x0.y, xn2 = -x0.z, xn3 = -x0.w;
    const float xn4 = -x1.x, xn5 = -x1.y, xn6 = -x1.z, xn7 = -x1.w;

    float best = 3.4e38f;
    int   bi   = 0;

    #pragma unroll 4
    for (int k = 0; k < BOOK; ++k) {
        float4 c0 = s_cb[2 * k + 0];
        float4 c1 = s_cb[2 * k + 1];
        float s = s_c2h[k];
        s = fmaf(xn0, c0.x, s);
        s = fmaf(xn1, c0.y, s);
        s = fmaf(xn2, c0.z, s);
        s = fmaf(xn3, c0.w, s);
        s = fmaf(xn4, c1.x, s);
        s = fmaf(xn5, c1.y, s);
        s = fmaf(xn6, c1.z, s);
        s = fmaf(xn7, c1.w, s);
        // strict < keeps FIRST minimum (matches jnp.argmin tie-break)
        if (s < best) { best = s; bi = k; }
    }

    s_idx[t] = (unsigned char)bi;

    // ---- cw_embed[b, c*8 .. c*8+7] = codebook[c, bi, :] (evict-first) ----
    float4* out4 = reinterpret_cast<float4*>(cw_embed + (size_t)b * CWDIM + c * DEMB);
    __stcs(out4 + 0, s_cb[2 * bi + 0]);
    __stcs(out4 + 1, s_cb[2 * bi + 1]);

    __syncthreads();

    // ---- one_hot fill: block owns rows (b0+r, c), r=0..255.
    // Each row: 256 floats = 64 float4. 256 threads -> 4 rows/iter, 64 iters.
    // Fully coalesced 512B/warp STG.128, streamed evict-first.
    const int off  = t & 63;   // float4 slot within row (k = off*4 .. off*4+3)
    const int rsub = t >> 6;   // row within the group of 4

    const int b0 = blockIdx.x * 256;
    float4* oh4 = reinterpret_cast<float4*>(one_hot)
                + (size_t)(b0 + rsub) * (CODES * BOOK / 4)
                + (size_t)c * (BOOK / 4)
                + off;
    const size_t step4 = (size_t)4 * (CODES * BOOK / 4);   // 4 b-rows per iter
    const unsigned kb = (unsigned)off * 4u;

    #pragma unroll 8
    for (int it = 0; it < 64; ++it) {
        const unsigned idx = s_idx[it * 4 + rsub];
        float4 v;
        v.x = (idx == kb + 0u) ? 1.0f : 0.0f;
        v.y = (idx == kb + 1u) ? 1.0f : 0.0f;
        v.z = (idx == kb + 2u) ? 1.0f : 0.0f;
        v.w = (idx == kb + 3u) ? 1.0f : 0.0f;
        __stcs(oh4, v);
        oh4 += step4;
    }
}

// ---------------------------------------------------------------------------
extern "C" void kernel_launch(void* const* d_in, const int* in_sizes, int n_in,
                              void* d_out, int out_size)
{
    const float* x  = (const float*)d_in[0];   // [4096, 1024]
    const float* cb = (const float*)d_in[1];   // [128, 256, 8]

    float* cw_embed = (float*)d_out;                               // [4096, 1024]
    float* one_hot  = (float*)d_out + (size_t)BATCH * CWDIM;       // [4096, 128, 256]

    dim3 grid(BATCH / 256, CODES);
    vq_fused_kernel<<<grid, 256>>>(x, cb, cw_embed, one_hot);
}

// round 6
// speedup vs baseline: 1.0829x; 1.0829x over previous
#include <cuda_runtime.h>
#include <cuda_bf16.h>
#include <cstdint>

// Problem constants (from reference setup_inputs)
#define BATCH  4096
#define CWDIM  1024
#define CODES  128     // C
#define BOOK   256     // K
#define DEMB   8       // D

#define THREADS 256
#define ROWS_PB 512    // two halves of 256

// ---------------------------------------------------------------------------
// Fused, software-pipelined kernel.
// grid = (BATCH/512, CODES), block = 256 threads, one c per block.
// Phase 0: argmin half A.  Phase 1: store one_hot(A) interleaved with
// argmin half B (1 store : 4 k-steps).  Phase 2: store one_hot(B).
// score(k) = 0.5*||c_k||^2 - x . c_k   (same argmin as full distance)
// ---------------------------------------------------------------------------
__global__ void __launch_bounds__(THREADS)
vq_fused_kernel(const float* __restrict__ x,
                const float* __restrict__ cb,
                float* __restrict__ cw_embed,
                float* __restrict__ one_hot)
{
    __shared__ float4        s_cb[BOOK * 2];   // codebook[c]: 256 x 8 floats
    __shared__ float         s_c2h[BOOK];      // 0.5 * ||c_k||^2
    __shared__ unsigned char s_idxA[256];
    __shared__ unsigned char s_idxB[256];

    const int c = blockIdx.y;
    const int t = threadIdx.x;
    const int b0 = blockIdx.x * ROWS_PB;

    // ---- Stage codebook[c] ----
    const float4* cb4 = reinterpret_cast<const float4*>(cb + (size_t)c * BOOK * DEMB);
    {
        float4 r0 = cb4[t * 2 + 0];
        float4 r1 = cb4[t * 2 + 1];
        s_cb[t * 2 + 0] = r0;
        s_cb[t * 2 + 1] = r1;
        s_c2h[t] = 0.5f * (r0.x * r0.x + r0.y * r0.y + r0.z * r0.z + r0.w * r0.w +
                           r1.x * r1.x + r1.y * r1.y + r1.z * r1.z + r1.w * r1.w);
    }

    // ---- Load x for both halves (rows b0+t and b0+256+t) ----
    const float4* xpA = reinterpret_cast<const float4*>(x + (size_t)(b0 + t) * CWDIM + c * DEMB);
    const float4* xpB = reinterpret_cast<const float4*>(x + (size_t)(b0 + 256 + t) * CWDIM + c * DEMB);
    float4 a0 = xpA[0], a1 = xpA[1];
    float4 e0 = xpB[0], e1 = xpB[1];
    const float an0 = -a0.x, an1 = -a0.y, an2 = -a0.z, an3 = -a0.w;
    const float an4 = -a1.x, an5 = -a1.y, an6 = -a1.z, an7 = -a1.w;
    const float bn0 = -e0.x, bn1 = -e0.y, bn2 = -e0.z, bn3 = -e0.w;
    const float bn4 = -e1.x, bn5 = -e1.y, bn6 = -e1.z, bn7 = -e1.w;

    __syncthreads();

    // ======== Phase 0: argmin half A ========
    float bestA = 3.4e38f;
    int   biA   = 0;
    #pragma unroll 4
    for (int k = 0; k < BOOK; ++k) {
        float4 c0 = s_cb[2 * k + 0];
        float4 c1 = s_cb[2 * k + 1];
        float s = s_c2h[k];
        s = fmaf(an0, c0.x, s);
        s = fmaf(an1, c0.y, s);
        s = fmaf(an2, c0.z, s);
        s = fmaf(an3, c0.w, s);
        s = fmaf(an4, c1.x, s);
        s = fmaf(an5, c1.y, s);
        s = fmaf(an6, c1.z, s);
        s = fmaf(an7, c1.w, s);
        if (s < bestA) { bestA = s; biA = k; }   // strict <, first-min tie-break
    }
    s_idxA[t] = (unsigned char)biA;

    // cw_embed half A
    {
        float4* o = reinterpret_cast<float4*>(cw_embed + (size_t)(b0 + t) * CWDIM + c * DEMB);
        o[0] = s_cb[2 * biA + 0];
        o[1] = s_cb[2 * biA + 1];
    }

    __syncthreads();

    // ======== Phase 1: store one_hot(A) interleaved with argmin half B ========
    const int off  = t & 63;   // float4 slot within a row
    const int rsub = t >> 6;   // which of 4 rows per store-iter
    const unsigned kb = (unsigned)off * 4u;
    const size_t step4 = (size_t)4 * (CODES * BOOK / 4);

    float4* ohA = reinterpret_cast<float4*>(one_hot)
                + (size_t)(b0 + rsub) * (CODES * BOOK / 4)
                + (size_t)c * (BOOK / 4) + off;

    float bestB = 3.4e38f;
    int   biB   = 0;

    #pragma unroll 2
    for (int it = 0; it < 64; ++it) {
        // one coalesced value store for half A
        {
            const unsigned idx = s_idxA[it * 4 + rsub];
            float4 v;
            v.x = (idx == kb + 0u) ? 1.0f : 0.0f;
            v.y = (idx == kb + 1u) ? 1.0f : 0.0f;
            v.z = (idx == kb + 2u) ? 1.0f : 0.0f;
            v.w = (idx == kb + 3u) ? 1.0f : 0.0f;
            *ohA = v;
            ohA += step4;
        }
        // four k-steps of half B argmin
        #pragma unroll
        for (int j = 0; j < 4; ++j) {
            const int k = it * 4 + j;
            float4 c0 = s_cb[2 * k + 0];
            float4 c1 = s_cb[2 * k + 1];
            float s = s_c2h[k];
            s = fmaf(bn0, c0.x, s);
            s = fmaf(bn1, c0.y, s);
            s = fmaf(bn2, c0.z, s);
            s = fmaf(bn3, c0.w, s);
            s = fmaf(bn4, c1.x, s);
            s = fmaf(bn5, c1.y, s);
            s = fmaf(bn6, c1.z, s);
            s = fmaf(bn7, c1.w, s);
            if (s < bestB) { bestB = s; biB = k; }
        }
    }
    s_idxB[t] = (unsigned char)biB;

    // cw_embed half B
    {
        float4* o = reinterpret_cast<float4*>(cw_embed + (size_t)(b0 + 256 + t) * CWDIM + c * DEMB);
        o[0] = s_cb[2 * biB + 0];
        o[1] = s_cb[2 * biB + 1];
    }

    __syncthreads();

    // ======== Phase 2: store one_hot(B) ========
    float4* ohB = reinterpret_cast<float4*>(one_hot)
                + (size_t)(b0 + 256 + rsub) * (CODES * BOOK / 4)
                + (size_t)c * (BOOK / 4) + off;

    #pragma unroll 8
    for (int it = 0; it < 64; ++it) {
        const unsigned idx = s_idxB[it * 4 + rsub];
        float4 v;
        v.x = (idx == kb + 0u) ? 1.0f : 0.0f;
        v.y = (idx == kb + 1u) ? 1.0f : 0.0f;
        v.z = (idx == kb + 2u) ? 1.0f : 0.0f;
        v.w = (idx == kb + 3u) ? 1.0f : 0.0f;
        *ohB = v;
        ohB += step4;
    }
}

// ---------------------------------------------------------------------------
extern "C" void kernel_launch(void* const* d_in, const int* in_sizes, int n_in,
                              void* d_out, int out_size)
{
    const float* x  = (const float*)d_in[0];   // [4096, 1024]
    const float* cb = (const float*)d_in[1];   // [128, 256, 8]

    float* cw_embed = (float*)d_out;                               // [4096, 1024]
    float* one_hot  = (float*)d_out + (size_t)BATCH * CWDIM;       // [4096, 128, 256]

    dim3 grid(BATCH / ROWS_PB, CODES);
    vq_fused_kernel<<<grid, THREADS>>>(x, cb, cw_embed, one_hot);
}

// round 7
// speedup vs baseline: 1.1667x; 1.0774x over previous
#include <cuda_runtime.h>
#include <cuda_bf16.h>
#include <cstdint>

// Problem constants (from reference setup_inputs)
#define BATCH  4096
#define CWDIM  1024
#define CODES  128     // C
#define BOOK   256     // K
#define DEMB   8       // D

#define THREADS 256
#define ROWS_PB 512    // 2 rows per thread

// ---------------------------------------------------------------------------
// Fused kernel (R2 store structure + LDS-lean argmin).
// grid = (BATCH/512, CODES), block = 256 threads, one c per block.
// Each thread argmins 2 rows; codebook broadcasts amortized over both.
// score(k) = 0.5*||c_k||^2 - x . c_k  (same argmin as full distance)
// ---------------------------------------------------------------------------
__global__ void __launch_bounds__(THREADS)
vq_fused_kernel(const float* __restrict__ x,
                const float* __restrict__ cb,
                float* __restrict__ cw_embed,
                float* __restrict__ one_hot)
{
    __shared__ float4        s_cb[BOOK * 2];     // codebook[c]: 256 x 8 floats
    __shared__ float4        s_h4[BOOK / 4];     // 0.5*||c||^2, 4 k's per float4
    __shared__ unsigned char s_idx[ROWS_PB];     // argmin index per local row

    const int c = blockIdx.y;
    const int t = threadIdx.x;
    const int b0 = blockIdx.x * ROWS_PB;

    // ---- Stage codebook[c] into smem ----
    const float4* cb4 = reinterpret_cast<const float4*>(cb + (size_t)c * BOOK * DEMB);
    {
        float4 r0 = cb4[t * 2 + 0];
        float4 r1 = cb4[t * 2 + 1];
        s_cb[t * 2 + 0] = r0;
        s_cb[t * 2 + 1] = r1;
        float h = 0.5f * (r0.x * r0.x + r0.y * r0.y + r0.z * r0.z + r0.w * r0.w +
                          r1.x * r1.x + r1.y * r1.y + r1.z * r1.z + r1.w * r1.w);
        reinterpret_cast<float*>(s_h4)[t] = h;   // h4[k>>2] lanes = k&3
    }

    // ---- Load x for this thread's 2 rows: b0+t and b0+256+t ----
    const float4* xpA = reinterpret_cast<const float4*>(x + (size_t)(b0 + t) * CWDIM + c * DEMB);
    const float4* xpB = reinterpret_cast<const float4*>(x + (size_t)(b0 + 256 + t) * CWDIM + c * DEMB);
    float4 a0 = xpA[0], a1 = xpA[1];
    float4 e0 = xpB[0], e1 = xpB[1];
    const float an0 = -a0.x, an1 = -a0.y, an2 = -a0.z, an3 = -a0.w;
    const float an4 = -a1.x, an5 = -a1.y, an6 = -a1.z, an7 = -a1.w;
    const float bn0 = -e0.x, bn1 = -e0.y, bn2 = -e0.z, bn3 = -e0.w;
    const float bn4 = -e1.x, bn5 = -e1.y, bn6 = -e1.z, bn7 = -e1.w;

    __syncthreads();

    // ---- Argmin over K=256 for both rows, 4 k's per outer iter ----
    float bestA = 3.4e38f, bestB = 3.4e38f;
    int   biA = 0, biB = 0;

    #pragma unroll 2
    for (int kq = 0; kq < BOOK / 4; ++kq) {
        const float4 h4 = s_h4[kq];
        const float hh[4] = {h4.x, h4.y, h4.z, h4.w};
        #pragma unroll
        for (int j = 0; j < 4; ++j) {
            const int k = kq * 4 + j;
            float4 c0 = s_cb[2 * k + 0];
            float4 c1 = s_cb[2 * k + 1];
            float sA = hh[j], sB = hh[j];
            sA = fmaf(an0, c0.x, sA);  sB = fmaf(bn0, c0.x, sB);
            sA = fmaf(an1, c0.y, sA);  sB = fmaf(bn1, c0.y, sB);
            sA = fmaf(an2, c0.z, sA);  sB = fmaf(bn2, c0.z, sB);
            sA = fmaf(an3, c0.w, sA);  sB = fmaf(bn3, c0.w, sB);
            sA = fmaf(an4, c1.x, sA);  sB = fmaf(bn4, c1.x, sB);
            sA = fmaf(an5, c1.y, sA);  sB = fmaf(bn5, c1.y, sB);
            sA = fmaf(an6, c1.z, sA);  sB = fmaf(bn6, c1.z, sB);
            sA = fmaf(an7, c1.w, sA);  sB = fmaf(bn7, c1.w, sB);
            // strict < keeps FIRST minimum (matches jnp.argmin tie-break)
            if (sA < bestA) { bestA = sA; biA = k; }
            if (sB < bestB) { bestB = sB; biB = k; }
        }
    }

    s_idx[t]       = (unsigned char)biA;
    s_idx[t + 256] = (unsigned char)biB;

    // ---- cw_embed for both rows ----
    {
        float4* oA = reinterpret_cast<float4*>(cw_embed + (size_t)(b0 + t) * CWDIM + c * DEMB);
        oA[0] = s_cb[2 * biA + 0];
        oA[1] = s_cb[2 * biA + 1];
        float4* oB = reinterpret_cast<float4*>(cw_embed + (size_t)(b0 + 256 + t) * CWDIM + c * DEMB);
        oB[0] = s_cb[2 * biB + 0];
        oB[1] = s_cb[2 * biB + 1];
    }

    __syncthreads();

    // ---- one_hot fill: 512 rows x 64 float4, R2 drain structure.
    // 256 threads -> 4 rows per iteration, 128 iterations, coalesced STG.128.
    const int off  = t & 63;   // float4 slot within row (k = off*4 .. off*4+3)
    const int rsub = t >> 6;   // row within group of 4
    const unsigned kb = (unsigned)off * 4u;

    float4* oh4 = reinterpret_cast<float4*>(one_hot)
                + (size_t)(b0 + rsub) * (CODES * BOOK / 4)
                + (size_t)c * (BOOK / 4)
                + off;
    const size_t step4 = (size_t)4 * (CODES * BOOK / 4);

    #pragma unroll 8
    for (int it = 0; it < ROWS_PB / 4; ++it) {
        const unsigned idx = s_idx[it * 4 + rsub];
        float4 v;
        v.x = (idx == kb + 0u) ? 1.0f : 0.0f;
        v.y = (idx == kb + 1u) ? 1.0f : 0.0f;
        v.z = (idx == kb + 2u) ? 1.0f : 0.0f;
        v.w = (idx == kb + 3u) ? 1.0f : 0.0f;
        *oh4 = v;
        oh4 += step4;
    }
}

// ---------------------------------------------------------------------------
extern "C" void kernel_launch(void* const* d_in, const int* in_sizes, int n_in,
                              void* d_out, int out_size)
{
    const float* x  = (const float*)d_in[0];   // [4096, 1024]
    const float* cb = (const float*)d_in[1];   // [128, 256, 8]

    float* cw_embed = (float*)d_out;                               // [4096, 1024]
    float* one_hot  = (float*)d_out + (size_t)BATCH * CWDIM;       // [4096, 128, 256]

    dim3 grid(BATCH / ROWS_PB, CODES);
    vq_fused_kernel<<<grid, THREADS>>>(x, cb, cw_embed, one_hot);
}